// round 7
// baseline (speedup 1.0000x reference)
#include <cuda_runtime.h>
#include <cuda_bf16.h>
#include <cstdint>

#define NN 200000
#define NE 400000
#define HS 128
#define ROW_TILES 1563            // ceil(200000/128)
#define NPAD (ROW_TILES * 128)    // 200064 padded rows
#define CHUNKS 196                // row-tile chunks: each CTA handles <=8 row tiles

#define LDA 136                   // padded smem row stride (elems)
#define ASZ (128 * LDA)           // elems per smem tile buffer
#define TSZ (ASZ * 2)             // bytes per smem tile buffer (34816)
// smem: B hi/lo resident + A 2 stages x (hi/lo) = 6 tile buffers
#define SMEM_BYTES (6 * TSZ)

// ---------------- scratch (device globals; no allocs allowed) ----------------
// NOTE: never passed as kernel args from host (host shadow + ATS trap);
// all resolution happens inside device code via `sel`.
__device__ float g_xall[(size_t)NN * 512];   // x@[w_iou;w_f]^T + bias  [N,512] = i|o|u|xf
__device__ float g_hu[(size_t)NN * HS];      // h_child @ u_f^T         [N,128]
__device__ float g_hsum[(size_t)NN * HS];    // segsum(h_child[src])    [N,128]
__device__ float g_fcsum[(size_t)NN * HS];   // segsum(f*c_child[src])  [N,128]
__device__ float g_uhsum[(size_t)NN * 384];  // hsum @ u_iou^T          [N,384]
// pre-split bf16 A operands (padded; tail rows stay zero from module-load init)
__device__ __align__(16) __nv_bfloat16 g_xhi[(size_t)NPAD * HS];
__device__ __align__(16) __nv_bfloat16 g_xlo[(size_t)NPAD * HS];
__device__ __align__(16) __nv_bfloat16 g_hhi[(size_t)NPAD * HS];
__device__ __align__(16) __nv_bfloat16 g_hlo[(size_t)NPAD * HS];
__device__ __align__(16) __nv_bfloat16 g_shi[(size_t)NPAD * HS];
__device__ __align__(16) __nv_bfloat16 g_slo[(size_t)NPAD * HS];
// packed bf16 weights, 8 tiles of [128 n][128 k] row-major:
// tiles 0-3: [w_iou;w_f] (512 rows), 4-6: u_iou (384), 7: u_f (128)
__device__ __align__(16) __nv_bfloat16 g_Bhi[8 * 16384];
__device__ __align__(16) __nv_bfloat16 g_Blo[8 * 16384];
__device__ __align__(16) float g_bias[512];

__device__ __forceinline__ float sigmoidf(float v) { return 1.0f / (1.0f + __expf(-v)); }

__device__ __forceinline__ uint32_t smem_u32(const void* p) {
    uint32_t a;
    asm("{ .reg .u64 t; cvta.to.shared.u64 t, %1; cvt.u32.u64 %0, t; }" : "=r"(a) : "l"(p));
    return a;
}

__device__ __forceinline__ void ldsm4(uint32_t* r, uint32_t addr) {
    asm volatile("ldmatrix.sync.aligned.m8n8.x4.shared.b16 {%0,%1,%2,%3}, [%4];"
                 : "=r"(r[0]), "=r"(r[1]), "=r"(r[2]), "=r"(r[3]) : "r"(addr));
}

__device__ __forceinline__ void mma16816(float* c, const uint32_t* a, uint32_t b0, uint32_t b1) {
    asm volatile(
        "mma.sync.aligned.m16n8k16.row.col.f32.bf16.bf16.f32 "
        "{%0,%1,%2,%3}, {%4,%5,%6,%7}, {%8,%9}, {%0,%1,%2,%3};"
        : "+f"(c[0]), "+f"(c[1]), "+f"(c[2]), "+f"(c[3])
        : "r"(a[0]), "r"(a[1]), "r"(a[2]), "r"(a[3]), "r"(b0), "r"(b1));
}

__device__ __forceinline__ void cp16(uint32_t dst, const void* src) {
    asm volatile("cp.async.cg.shared.global [%0], [%1], 16;" :: "r"(dst), "l"(src));
}
__device__ __forceinline__ void cp_commit() {
    asm volatile("cp.async.commit_group;");
}
template <int N>
__device__ __forceinline__ void cp_wait() {
    asm volatile("cp.async.wait_group %0;" :: "n"(N));
}

__device__ __forceinline__ uint32_t pack2(__nv_bfloat16 lo, __nv_bfloat16 hi) {
    return (uint32_t)__bfloat16_as_ushort(lo) | ((uint32_t)__bfloat16_as_ushort(hi) << 16);
}

// ---------------- zero the accumulators ----------------
__global__ void k_zero() {
    int i = blockIdx.x * blockDim.x + threadIdx.x;
    const int total4 = NN * HS / 4;
    if (i < total4) {
        float4 z = make_float4(0.f, 0.f, 0.f, 0.f);
        reinterpret_cast<float4*>(g_hsum)[i] = z;
        reinterpret_cast<float4*>(g_fcsum)[i] = z;
    }
}

// ---------------- split fp32 -> bf16 hi/lo (4 elems per thread) ----------------
// sel 0: src=ext (x)       -> g_xhi/g_xlo
// sel 1: src=ext (h_child) -> g_hhi/g_hlo
// sel 2: src=g_hsum        -> g_shi/g_slo
__global__ void k_split(const float* __restrict__ ext, int sel) {
    const int total4 = NN * HS / 4;
    int i = blockIdx.x * blockDim.x + threadIdx.x;
    if (i >= total4) return;
    const float* src = (sel == 2) ? g_hsum : ext;
    __nv_bfloat16* hi = (sel == 0) ? g_xhi : (sel == 1) ? g_hhi : g_shi;
    __nv_bfloat16* lo = (sel == 0) ? g_xlo : (sel == 1) ? g_hlo : g_slo;
    float4 v = reinterpret_cast<const float4*>(src)[i];
    float f[4] = {v.x, v.y, v.z, v.w};
    uint32_t hp[2], lp[2];
#pragma unroll
    for (int p = 0; p < 2; p++) {
        __nv_bfloat16 h0 = __float2bfloat16(f[2 * p]);
        __nv_bfloat16 h1 = __float2bfloat16(f[2 * p + 1]);
        __nv_bfloat16 l0 = __float2bfloat16(f[2 * p] - __bfloat162float(h0));
        __nv_bfloat16 l1 = __float2bfloat16(f[2 * p + 1] - __bfloat162float(h1));
        hp[p] = pack2(h0, h1);
        lp[p] = pack2(l0, l1);
    }
    reinterpret_cast<uint2*>(hi)[i] = make_uint2(hp[0], hp[1]);
    reinterpret_cast<uint2*>(lo)[i] = make_uint2(lp[0], lp[1]);
}

// ---------------- pack weights: fp32 -> bf16 hi/lo, row-major [n][k] tiles ----------------
__global__ void k_prep(const float* __restrict__ w_iou, const float* __restrict__ w_f,
                       const float* __restrict__ u_iou, const float* __restrict__ u_f,
                       const float* __restrict__ b_iou, const float* __restrict__ b_f) {
    int i = blockIdx.x * blockDim.x + threadIdx.x;
    if (i < 512) g_bias[i] = (i < 384) ? b_iou[i] : b_f[i - 384];
    if (i >= 131072) return;
    int n, k, tile;
    float val;
    if (i < 65536) {                       // [w_iou ; w_f], 512 rows
        n = i >> 7; k = i & 127;
        tile = n >> 7;
        val = (n < 384) ? w_iou[n * 128 + k] : w_f[(n - 384) * 128 + k];
    } else if (i < 65536 + 49152) {        // u_iou, 384 rows
        int j = i - 65536;
        n = j >> 7; k = j & 127;
        tile = 4 + (n >> 7);
        val = u_iou[n * 128 + k];
    } else {                               // u_f, 128 rows
        int j = i - 114688;
        n = j >> 7; k = j & 127;
        tile = 7;
        val = u_f[n * 128 + k];
    }
    __nv_bfloat16 hi = __float2bfloat16(val);
    __nv_bfloat16 lo = __float2bfloat16(val - __bfloat162float(hi));
    int off = tile * 16384 + (n & 127) * 128 + k;
    g_Bhi[off] = hi;
    g_Blo[off] = lo;
}

// copy one [128][128] bf16 tile, global row-major -> smem padded LDA, via cp.async
__device__ __forceinline__ void copy_tile(uint32_t sdst, const __nv_bfloat16* gsrc, int tid) {
#pragma unroll
    for (int it = 0; it < 8; it++) {
        int j = tid + it * 256;        // 2048 16B chunks
        int r = j >> 4, c = j & 15;
        cp16(sdst + (uint32_t)(r * LDA + c * 8) * 2, gsrc + r * 128 + c * 8);
    }
}

// ============================================================================
// bf16 mma.sync GEMM: B (one gate col-tile) resident in smem; A row-tiles
// streamed with 2-stage cp.async double buffer. Each CTA handles <=8 row tiles
// (rt = blockIdx.x + t*CHUNKS).
// phase 0, y<4:  A=x      -> g_xall  gate y   (stride 512, +bias, btile y)
// phase 0, y==4: A=h      -> g_hu             (stride 128, btile 7)
// phase 1:       A=hsum   -> g_uhsum gate y   (stride 384, btile 4+y)
// 3-term split: Ahi*Bhi + Ahi*Blo + Alo*Bhi.
// ============================================================================
__global__ void __launch_bounds__(256) k_mma(int phase) {
    const int y = blockIdx.y;
    int sel, gate;
    if (phase == 0) { sel = (y < 4) ? 0 : 1; gate = (y < 4) ? y : 0; }
    else            { sel = 2; gate = y; }

    const __nv_bfloat16* Ahi = (sel == 0) ? g_xhi : (sel == 1) ? g_hhi : g_shi;
    const __nv_bfloat16* Alo = (sel == 0) ? g_xlo : (sel == 1) ? g_hlo : g_slo;
    float* out = (sel == 0) ? g_xall : (sel == 1) ? g_hu : g_uhsum;
    const int ostride = (sel == 0) ? 512 : (sel == 1) ? 128 : 384;
    const int btile   = (sel == 0) ? gate : (sel == 1) ? 7 : (4 + gate);
    const int colbase = gate * 128;
    const int usebias = (sel == 0);

    extern __shared__ __nv_bfloat16 sm[];
    const int tid = threadIdx.x;
    const int lane = tid & 31, wid = tid >> 5;

    const uint32_t sBase = smem_u32(sm);
    const uint32_t sB = sBase;               // B: hi at sB, lo at sB+TSZ
    const uint32_t sA = sBase + 2 * TSZ;     // A stage s: hi at sA+s*2*TSZ, lo +TSZ

    // prologue: resident B + first A tile (one commit group)
    copy_tile(sB, g_Bhi + (size_t)btile * 16384, tid);
    copy_tile(sB + TSZ, g_Blo + (size_t)btile * 16384, tid);
    copy_tile(sA, Ahi + (size_t)blockIdx.x * 16384, tid);
    copy_tile(sA + TSZ, Alo + (size_t)blockIdx.x * 16384, tid);
    cp_commit();

    // ---- warp tiling: 4x2 warps, each 32 rows x 64 cols ----
    const int wr = wid & 3;
    const int wcol = wid >> 2;
    const int aRow = wr * 32 + (lane & 15);
    const int aK   = (lane >> 4) * 8;
    const int gg   = lane >> 3;
    const int bRow = wcol * 64 + (gg >> 1) * 8 + (lane & 7);
    const int bK   = (gg & 1) * 8;
    const uint32_t aOffB = (uint32_t)(aRow * LDA + aK) * 2;
    const uint32_t bHiB = sB + (uint32_t)(bRow * LDA + bK) * 2;
    const uint32_t bLoB = bHiB + TSZ;

    for (int t = 0;; t++) {
        const int rt = blockIdx.x + t * CHUNKS;
        const int rn = rt + CHUNKS;
        const bool more = (rn < ROW_TILES);
        if (more) {
            uint32_t st = sA + ((t + 1) & 1) * 2 * TSZ;
            copy_tile(st, Ahi + (size_t)rn * 16384, tid);
            copy_tile(st + TSZ, Alo + (size_t)rn * 16384, tid);
            cp_commit();
            cp_wait<1>();
        } else {
            cp_wait<0>();
        }
        __syncthreads();

        const uint32_t aHiB = sA + (t & 1) * 2 * TSZ + aOffB;
        const uint32_t aLoB = aHiB + TSZ;

        float acc[2][8][4];
#pragma unroll
        for (int i = 0; i < 2; i++)
#pragma unroll
            for (int j = 0; j < 8; j++)
#pragma unroll
                for (int q = 0; q < 4; q++) acc[i][j][q] = 0.f;

#pragma unroll
        for (int t3 = 0; t3 < 3; t3++) {
            const uint32_t aBase = (t3 == 2) ? aLoB : aHiB;
            const uint32_t bBase = (t3 == 1) ? bLoB : bHiB;
#pragma unroll
            for (int kb = 0; kb < 8; kb++) {
                uint32_t a[2][4];
                ldsm4(a[0], aBase + kb * 32);
                ldsm4(a[1], aBase + 16 * LDA * 2 + kb * 32);
                uint32_t b[4][4];
#pragma unroll
                for (int p = 0; p < 4; p++)
                    ldsm4(b[p], bBase + p * 16 * LDA * 2 + kb * 32);
#pragma unroll
                for (int i = 0; i < 2; i++)
#pragma unroll
                    for (int j = 0; j < 8; j++)
                        mma16816(acc[i][j], a[i], b[j >> 1][(j & 1) * 2], b[j >> 1][(j & 1) * 2 + 1]);
            }
        }

        // ---- epilogue for this row tile ----
        const int brow = rt * 128;
        const int colb = colbase + wcol * 64;
#pragma unroll
        for (int i = 0; i < 2; i++) {
            int row0 = brow + wr * 32 + i * 16 + (lane >> 2);
            int row1 = row0 + 8;
#pragma unroll
            for (int j = 0; j < 8; j++) {
                int col = colb + j * 8 + (lane & 3) * 2;
                float bx = 0.f, by = 0.f;
                if (usebias) { bx = g_bias[col]; by = g_bias[col + 1]; }
                if (row0 < NN) {
                    float2 v = make_float2(acc[i][j][0] + bx, acc[i][j][1] + by);
                    *reinterpret_cast<float2*>(out + (size_t)row0 * ostride + col) = v;
                }
                if (row1 < NN) {
                    float2 v = make_float2(acc[i][j][2] + bx, acc[i][j][3] + by);
                    *reinterpret_cast<float2*>(out + (size_t)row1 * ostride + col) = v;
                }
            }
        }
        __syncthreads();   // protect next prefetch's target buffer
        if (!more) break;
    }
}

// ---------------- edge pass: one warp per edge, pure gather/scatter ----------------
__global__ void k_edge(const float* __restrict__ h_child, const float* __restrict__ c_child,
                       const int* __restrict__ esrc, const int* __restrict__ edst) {
    int idx = blockIdx.x * blockDim.x + threadIdx.x;
    int e = idx >> 5;
    int q = idx & 31;
    if (e >= NE) return;
    int s = esrc[e];
    int d = edst[e];
    float4 h4  = reinterpret_cast<const float4*>(h_child + (size_t)s * HS)[q];
    float4 hu4 = reinterpret_cast<const float4*>(g_hu + (size_t)s * HS)[q];
    float4 c4  = reinterpret_cast<const float4*>(c_child + (size_t)s * HS)[q];
    float4 xf4 = reinterpret_cast<const float4*>(g_xall + (size_t)d * 512 + 384)[q];
    float* hs = g_hsum + (size_t)d * HS + q * 4;
    float* fc = g_fcsum + (size_t)d * HS + q * 4;
    atomicAdd(hs + 0, h4.x); atomicAdd(hs + 1, h4.y);
    atomicAdd(hs + 2, h4.z); atomicAdd(hs + 3, h4.w);
    atomicAdd(fc + 0, sigmoidf(xf4.x + hu4.x) * c4.x);
    atomicAdd(fc + 1, sigmoidf(xf4.y + hu4.y) * c4.y);
    atomicAdd(fc + 2, sigmoidf(xf4.z + hu4.z) * c4.z);
    atomicAdd(fc + 3, sigmoidf(xf4.w + hu4.w) * c4.w);
}

// ---------------- final node update ----------------
__global__ void k_final(float* __restrict__ out) {
    int idx = blockIdx.x * blockDim.x + threadIdx.x;
    if (idx >= NN * HS) return;
    int n = idx >> 7;
    int j = idx & 127;
    size_t bx = (size_t)n * 512;
    size_t bu = (size_t)n * 384;
    float i_ = sigmoidf(g_xall[bx + j]       + g_uhsum[bu + j]);
    float o_ = sigmoidf(g_xall[bx + 128 + j] + g_uhsum[bu + 128 + j]);
    float u_ = tanhf(   g_xall[bx + 256 + j] + g_uhsum[bu + 256 + j]);
    float c = i_ * u_ + g_fcsum[idx];
    float h = o_ * tanhf(c);
    out[idx] = h;
    out[(size_t)NN * HS + idx] = c;
}

// ============================================================================
extern "C" void kernel_launch(void* const* d_in, const int* in_sizes, int n_in,
                              void* d_out, int out_size) {
    const float* x       = (const float*)d_in[0];
    const float* h_child = (const float*)d_in[1];
    const float* c_child = (const float*)d_in[2];
    const float* w_iou   = (const float*)d_in[3];
    const float* b_iou   = (const float*)d_in[4];
    const float* w_f     = (const float*)d_in[5];
    const float* b_f     = (const float*)d_in[6];
    const float* u_iou   = (const float*)d_in[7];
    const float* u_f     = (const float*)d_in[8];
    const int*   esrc    = (const int*)d_in[9];
    const int*   edst    = (const int*)d_in[10];
    float* out = (float*)d_out;

    static bool configured = false;
    if (!configured) {
        cudaFuncSetAttribute(k_mma, cudaFuncAttributeMaxDynamicSharedMemorySize, SMEM_BYTES);
        configured = true;
    }

    const int total4 = NN * HS / 4;
    const int sgrid = (total4 + 255) / 256;

    k_zero<<<(total4 + 255) / 256, 256>>>();
    k_prep<<<131072 / 256, 256>>>(w_iou, w_f, u_iou, u_f, b_iou, b_f);
    k_split<<<sgrid, 256>>>(x, 0);
    k_split<<<sgrid, 256>>>(h_child, 1);
    k_mma<<<dim3(CHUNKS, 5), 256, SMEM_BYTES>>>(0);   // x->g_xall (4 gates) + h->g_hu
    k_edge<<<(NE * 32) / 256, 256>>>(h_child, c_child, esrc, edst);
    k_split<<<sgrid, 256>>>(nullptr, 2);
    k_mma<<<dim3(CHUNKS, 3), 256, SMEM_BYTES>>>(1);   // g_hsum -> g_uhsum (3 gates)
    k_final<<<(NN * HS + 255) / 256, 256>>>(out);
}